// round 7
// baseline (speedup 1.0000x reference)
#include <cuda_runtime.h>
#include <cuda_bf16.h>

// SentimentNetEnd2End: per-element tiny LSTM (T steps, I=H=3) + 2x cosine sim.
// R7: TWO batch elements per thread (interleaved independent recurrences) to
// fill dependency-stall slots (R6 measured issue=24.5% with 1 warp/SMSP).
// Keeps R6's MUFU tanh nonlinearities + fma.rn.f32x2 gate-pair matvec.

typedef unsigned long long u64;

__device__ __forceinline__ float tanha(float x) {
    float y; asm("tanh.approx.f32 %0, %1;" : "=f"(y) : "f"(x)); return y;
}
__device__ __forceinline__ u64 pk2(float lo, float hi) {
    u64 r; asm("mov.b64 %0, {%1, %2};" : "=l"(r) : "f"(lo), "f"(hi)); return r;
}
__device__ __forceinline__ void upk2(float& lo, float& hi, u64 v) {
    asm("mov.b64 {%0, %1}, %2;" : "=f"(lo), "=f"(hi) : "l"(v));
}
__device__ __forceinline__ u64 fma2(u64 a, u64 b, u64 c) {
    u64 d; asm("fma.rn.f32x2 %0, %1, %2, %3;" : "=l"(d) : "l"(a), "l"(b), "l"(c));
    return d;
}

__global__ __launch_bounds__(64, 1)
void lstm_cos_kernel(const float* __restrict__ story,
                     const float* __restrict__ e1g,
                     const float* __restrict__ e2g,
                     const float* __restrict__ Wih,
                     const float* __restrict__ Whh,
                     const float* __restrict__ bih,
                     const float* __restrict__ bhh,
                     float* __restrict__ out,
                     int B, int T)
{
    int t = blockIdx.x * blockDim.x + threadIdx.x;
    int nPairs = B >> 1;
    if (t >= nPairs) return;
    int bA = 2 * t;
    int bB = 2 * t + 1;

    // Rows 0-2:i, 3-5:f, 6-8:g, 9-11:o. Sigmoid rows (i,f,o) pre-scaled by 0.5
    // (sigmoid(z)=0.5*tanh(z/2)+0.5); tanh rows (g) unscaled.
    // Gate-pair packed: slot r -> gates (2r, 2r+1). Shared by both elements.
    u64 WI0[6], WI1[6], WI2[6], WH0[6], WH1[6], WH2[6], BS[6];
#pragma unroll
    for (int r = 0; r < 6; r++) {
        int g0 = 2 * r, g1 = 2 * r + 1;
        float s0 = (g0 >= 6 && g0 < 9) ? 1.0f : 0.5f;
        float s1 = (g1 >= 6 && g1 < 9) ? 1.0f : 0.5f;
        WI0[r] = pk2(__ldg(&Wih[g0 * 3 + 0]) * s0, __ldg(&Wih[g1 * 3 + 0]) * s1);
        WI1[r] = pk2(__ldg(&Wih[g0 * 3 + 1]) * s0, __ldg(&Wih[g1 * 3 + 1]) * s1);
        WI2[r] = pk2(__ldg(&Wih[g0 * 3 + 2]) * s0, __ldg(&Wih[g1 * 3 + 2]) * s1);
        WH0[r] = pk2(__ldg(&Whh[g0 * 3 + 0]) * s0, __ldg(&Whh[g1 * 3 + 0]) * s1);
        WH1[r] = pk2(__ldg(&Whh[g0 * 3 + 1]) * s0, __ldg(&Whh[g1 * 3 + 1]) * s1);
        WH2[r] = pk2(__ldg(&Whh[g0 * 3 + 2]) * s0, __ldg(&Whh[g1 * 3 + 2]) * s1);
        BS[r]  = pk2((__ldg(&bih[g0]) + __ldg(&bhh[g0])) * s0,
                     (__ldg(&bih[g1]) + __ldg(&bhh[g1])) * s1);
    }

    float hA0 = 0.f, hA1 = 0.f, hA2 = 0.f;
    float hB0 = 0.f, hB1 = 0.f, hB2 = 0.f;
    float cA[3] = {0.f, 0.f, 0.f};
    float cB[3] = {0.f, 0.f, 0.f};

    // One merged LSTM step for both elements; independent chains interleave.
#define STEP_PAIR(xA0, xA1, xA2, xB0, xB1, xB2) do {                           \
        u64 XA0 = pk2((xA0), (xA0)), XA1 = pk2((xA1), (xA1));                  \
        u64 XA2 = pk2((xA2), (xA2));                                           \
        u64 XB0 = pk2((xB0), (xB0)), XB1 = pk2((xB1), (xB1));                  \
        u64 XB2 = pk2((xB2), (xB2));                                           \
        u64 HA0 = pk2(hA0, hA0), HA1 = pk2(hA1, hA1), HA2 = pk2(hA2, hA2);     \
        u64 HB0 = pk2(hB0, hB0), HB1 = pk2(hB1, hB1), HB2 = pk2(hB2, hB2);     \
        u64 uvA[6], uvB[6];                                                    \
        _Pragma("unroll")                                                      \
        for (int r = 0; r < 6; r++) {                                          \
            uvA[r] = fma2(WI0[r], XA0, fma2(WI1[r], XA1, fma2(WI2[r], XA2,     \
                     fma2(WH0[r], HA0, fma2(WH1[r], HA1,                       \
                     fma2(WH2[r], HA2, BS[r]))))));                            \
            uvB[r] = fma2(WI0[r], XB0, fma2(WI1[r], XB1, fma2(WI2[r], XB2,     \
                     fma2(WH0[r], HB0, fma2(WH1[r], HB1,                       \
                     fma2(WH2[r], HB2, BS[r]))))));                            \
        }                                                                      \
        float uA[12], uB[12];                                                  \
        _Pragma("unroll")                                                      \
        for (int r = 0; r < 6; r++) {                                          \
            upk2(uA[2 * r], uA[2 * r + 1], uvA[r]);                            \
            upk2(uB[2 * r], uB[2 * r + 1], uvB[r]);                            \
        }                                                                      \
        float hnA[3], hnB[3];                                                  \
        _Pragma("unroll")                                                      \
        for (int j = 0; j < 3; j++) {                                          \
            float tiA = tanha(uA[j]);                                          \
            float tiB = tanha(uB[j]);                                          \
            float tfA = tanha(uA[3 + j]);                                      \
            float tfB = tanha(uB[3 + j]);                                      \
            float ggA = tanha(uA[6 + j]);                                      \
            float ggB = tanha(uB[6 + j]);                                      \
            float toA = tanha(uA[9 + j]);                                      \
            float toB = tanha(uB[9 + j]);                                      \
            float igA = fmaf(0.5f, tiA, 0.5f);                                 \
            float igB = fmaf(0.5f, tiB, 0.5f);                                 \
            float fgA = fmaf(0.5f, tfA, 0.5f);                                 \
            float fgB = fmaf(0.5f, tfB, 0.5f);                                 \
            float ccA = fmaf(fgA, cA[j], igA * ggA);                           \
            float ccB = fmaf(fgB, cB[j], igB * ggB);                           \
            cA[j] = ccA;                                                       \
            cB[j] = ccB;                                                       \
            float thA = tanha(ccA);                                            \
            float thB = tanha(ccB);                                            \
            hnA[j] = 0.5f * fmaf(toA, thA, thA);                               \
            hnB[j] = 0.5f * fmaf(toB, thB, thB);                               \
        }                                                                      \
        hA0 = hnA[0]; hA1 = hnA[1]; hA2 = hnA[2];                              \
        hB0 = hnB[0]; hB1 = hnB[1]; hB2 = hnB[2];                              \
    } while (0)

    const float4* xpA = reinterpret_cast<const float4*>(
        story + (size_t)bA * (size_t)T * 3u);
    const float4* xpB = reinterpret_cast<const float4*>(
        story + (size_t)bB * (size_t)T * 3u);
    int nIter = (T * 3) / 12;  // 4 steps (12 floats = 3 float4) per iteration

    float4 caA = xpA[0], cbA = xpA[1], cdA = xpA[2];
    float4 caB = xpB[0], cbB = xpB[1], cdB = xpB[2];
    for (int it = 1; it <= nIter; ++it) {
        float4 naA, nbA, ndA, naB, nbB, ndB;
        if (it < nIter) {              // prefetch next 4-step group
            naA = xpA[3 * it + 0]; nbA = xpA[3 * it + 1]; ndA = xpA[3 * it + 2];
            naB = xpB[3 * it + 0]; nbB = xpB[3 * it + 1]; ndB = xpB[3 * it + 2];
        } else {
            naA = caA; nbA = cbA; ndA = cdA;  // dead values on last iteration
            naB = caB; nbB = cbB; ndB = cdB;
        }
        STEP_PAIR(caA.x, caA.y, caA.z, caB.x, caB.y, caB.z);
        STEP_PAIR(caA.w, cbA.x, cbA.y, caB.w, cbB.x, cbB.y);
        STEP_PAIR(cbA.z, cbA.w, cdA.x, cbB.z, cbB.w, cdB.x);
        STEP_PAIR(cdA.y, cdA.z, cdA.w, cdB.y, cdB.z, cdB.w);
        caA = naA; cbA = nbA; cdA = ndA;
        caB = naB; cbB = nbB; cdB = ndB;
    }
#undef STEP_PAIR

    // Cosine similarities (torch CosineSimilarity semantics, eps=1e-8).
    {
        float nh = fmaxf(sqrtf(hA0 * hA0 + hA1 * hA1 + hA2 * hA2), 1e-8f);
        float a0 = __ldg(&e1g[3 * bA + 0]);
        float a1 = __ldg(&e1g[3 * bA + 1]);
        float a2 = __ldg(&e1g[3 * bA + 2]);
        float n1 = fmaxf(sqrtf(a0 * a0 + a1 * a1 + a2 * a2), 1e-8f);
        float d1 = hA0 * a0 + hA1 * a1 + hA2 * a2;
        float b0 = __ldg(&e2g[3 * bA + 0]);
        float b1 = __ldg(&e2g[3 * bA + 1]);
        float b2 = __ldg(&e2g[3 * bA + 2]);
        float n2 = fmaxf(sqrtf(b0 * b0 + b1 * b1 + b2 * b2), 1e-8f);
        float d2 = hA0 * b0 + hA1 * b1 + hA2 * b2;
        out[2 * bA + 0] = d1 / (nh * n1);
        out[2 * bA + 1] = d2 / (nh * n2);
    }
    {
        float nh = fmaxf(sqrtf(hB0 * hB0 + hB1 * hB1 + hB2 * hB2), 1e-8f);
        float a0 = __ldg(&e1g[3 * bB + 0]);
        float a1 = __ldg(&e1g[3 * bB + 1]);
        float a2 = __ldg(&e1g[3 * bB + 2]);
        float n1 = fmaxf(sqrtf(a0 * a0 + a1 * a1 + a2 * a2), 1e-8f);
        float d1 = hB0 * a0 + hB1 * a1 + hB2 * a2;
        float b0 = __ldg(&e2g[3 * bB + 0]);
        float b1 = __ldg(&e2g[3 * bB + 1]);
        float b2 = __ldg(&e2g[3 * bB + 2]);
        float n2 = fmaxf(sqrtf(b0 * b0 + b1 * b1 + b2 * b2), 1e-8f);
        float d2 = hB0 * b0 + hB1 * b1 + hB2 * b2;
        out[2 * bB + 0] = d1 / (nh * n1);
        out[2 * bB + 1] = d2 / (nh * n2);
    }
}

extern "C" void kernel_launch(void* const* d_in, const int* in_sizes, int n_in,
                              void* d_out, int out_size)
{
    const float* story = (const float*)d_in[0];
    const float* e1    = (const float*)d_in[1];
    const float* e2    = (const float*)d_in[2];
    const float* Wih   = (const float*)d_in[3];
    const float* Whh   = (const float*)d_in[4];
    const float* bih   = (const float*)d_in[5];
    const float* bhh   = (const float*)d_in[6];

    int B = in_sizes[1] / 3;                 // ending1_emb is [B,3]
    int T = in_sizes[0] / (B * 3);           // story_emb is [B,T,3]

    int nPairs  = B / 2;
    int threads = 64;                        // 1 warp/SMSP, more SMs active
    int blocks  = (nPairs + threads - 1) / threads;
    lstm_cos_kernel<<<blocks, threads>>>(story, e1, e2, Wih, Whh, bih, bhh,
                                         (float*)d_out, B, T);
}

// round 8
// speedup vs baseline: 1.4322x; 1.4322x over previous
#include <cuda_runtime.h>
#include <cuda_bf16.h>

// SentimentNetEnd2End: per-element tiny LSTM (T steps, I=H=3) + 2x cosine sim.
// R8: revert to 1 elem/thread (512 warps = max SMSP coverage; R7 proved the
// binding pipe is per-SMSP MUFU with TANH rt~16). Shave exposed latency:
//  - loop-carried xpart: next step's WI*x+b computed during current tanh window
//  - H' = 2h tracked instead of h (cosine is scale-invariant) -> H'=fma(to,th,th)
//    with WH pre-scaled by an extra 0.5.
// Keeps MUFU tanh nonlinearities + fma.rn.f32x2 packed matvec.

typedef unsigned long long u64;

__device__ __forceinline__ float tanha(float x) {
    float y; asm("tanh.approx.f32 %0, %1;" : "=f"(y) : "f"(x)); return y;
}
__device__ __forceinline__ u64 pk2(float lo, float hi) {
    u64 r; asm("mov.b64 %0, {%1, %2};" : "=l"(r) : "f"(lo), "f"(hi)); return r;
}
__device__ __forceinline__ void upk2(float& lo, float& hi, u64 v) {
    asm("mov.b64 {%0, %1}, %2;" : "=f"(lo), "=f"(hi) : "l"(v));
}
__device__ __forceinline__ u64 fma2(u64 a, u64 b, u64 c) {
    u64 d; asm("fma.rn.f32x2 %0, %1, %2, %3;" : "=l"(d) : "l"(a), "l"(b), "l"(c));
    return d;
}

__global__ __launch_bounds__(128, 1)
void lstm_cos_kernel(const float* __restrict__ story,
                     const float* __restrict__ e1g,
                     const float* __restrict__ e2g,
                     const float* __restrict__ Wih,
                     const float* __restrict__ Whh,
                     const float* __restrict__ bih,
                     const float* __restrict__ bhh,
                     float* __restrict__ out,
                     int B, int T)
{
    int b = blockIdx.x * blockDim.x + threadIdx.x;
    if (b >= B) return;

    // Rows 0-2:i, 3-5:f, 6-8:g, 9-11:o.
    // Sigmoid rows (i,f,o) scaled 0.5 (sigmoid(z)=0.5*tanh(z/2)+0.5); g unscaled.
    // WH additionally scaled 0.5 because the carried hidden state is H'=2h.
    // Gate-pair packed: slot r -> gates (2r, 2r+1).
    u64 WI0[6], WI1[6], WI2[6], WH0[6], WH1[6], WH2[6], BS[6];
#pragma unroll
    for (int r = 0; r < 6; r++) {
        int g0 = 2 * r, g1 = 2 * r + 1;
        float s0 = (g0 >= 6 && g0 < 9) ? 1.0f : 0.5f;
        float s1 = (g1 >= 6 && g1 < 9) ? 1.0f : 0.5f;
        float t0 = 0.5f * s0, t1 = 0.5f * s1;   // extra 0.5 for H'=2h
        WI0[r] = pk2(__ldg(&Wih[g0 * 3 + 0]) * s0, __ldg(&Wih[g1 * 3 + 0]) * s1);
        WI1[r] = pk2(__ldg(&Wih[g0 * 3 + 1]) * s0, __ldg(&Wih[g1 * 3 + 1]) * s1);
        WI2[r] = pk2(__ldg(&Wih[g0 * 3 + 2]) * s0, __ldg(&Wih[g1 * 3 + 2]) * s1);
        WH0[r] = pk2(__ldg(&Whh[g0 * 3 + 0]) * t0, __ldg(&Whh[g1 * 3 + 0]) * t1);
        WH1[r] = pk2(__ldg(&Whh[g0 * 3 + 1]) * t0, __ldg(&Whh[g1 * 3 + 1]) * t1);
        WH2[r] = pk2(__ldg(&Whh[g0 * 3 + 2]) * t0, __ldg(&Whh[g1 * 3 + 2]) * t1);
        BS[r]  = pk2((__ldg(&bih[g0]) + __ldg(&bhh[g0])) * s0,
                     (__ldg(&bih[g1]) + __ldg(&bhh[g1])) * s1);
    }

    float h0 = 0.f, h1 = 0.f, h2 = 0.f;      // H' = 2h
    float c[3] = {0.f, 0.f, 0.f};
    u64 XP[6];                                // xpart for the UPCOMING step

    // One LSTM step. Consumes XP (this step's WI*x+b), produces XP for the
    // next step from (xn0,xn1,xn2) — independent of h, so it fills the MUFU
    // tanh window.
#define STEP(xn0, xn1, xn2) do {                                               \
        u64 H0 = pk2(h0, h0), H1 = pk2(h1, h1), H2 = pk2(h2, h2);              \
        u64 uv[6];                                                             \
        _Pragma("unroll")                                                      \
        for (int r = 0; r < 6; r++)                                            \
            uv[r] = fma2(WH0[r], H0, fma2(WH1[r], H1,                          \
                    fma2(WH2[r], H2, XP[r])));                                 \
        float u[12];                                                           \
        _Pragma("unroll")                                                      \
        for (int r = 0; r < 6; r++) upk2(u[2 * r], u[2 * r + 1], uv[r]);       \
        float ti[3], tf[3], gg[3], to[3];                                      \
        _Pragma("unroll")                                                      \
        for (int j = 0; j < 3; j++) {                                          \
            ti[j] = tanha(u[j]);                                               \
            tf[j] = tanha(u[3 + j]);                                           \
            gg[j] = tanha(u[6 + j]);                                           \
            to[j] = tanha(u[9 + j]);                                           \
        }                                                                      \
        {   /* next step's x-projection: fills the MUFU shadow */              \
            u64 X0 = pk2((xn0), (xn0));                                        \
            u64 X1 = pk2((xn1), (xn1));                                        \
            u64 X2 = pk2((xn2), (xn2));                                        \
            _Pragma("unroll")                                                  \
            for (int r = 0; r < 6; r++)                                        \
                XP[r] = fma2(WI0[r], X0, fma2(WI1[r], X1,                      \
                        fma2(WI2[r], X2, BS[r])));                             \
        }                                                                      \
        float hn[3];                                                           \
        _Pragma("unroll")                                                      \
        for (int j = 0; j < 3; j++) {                                          \
            float ig = fmaf(0.5f, ti[j], 0.5f);                                \
            float fg = fmaf(0.5f, tf[j], 0.5f);                                \
            float cc = fmaf(fg, c[j], ig * gg[j]);                             \
            c[j] = cc;                                                         \
            float th = tanha(cc);                                              \
            hn[j] = fmaf(to[j], th, th);       /* H' = 2h = th*(to+1) */       \
        }                                                                      \
        h0 = hn[0]; h1 = hn[1]; h2 = hn[2];                                    \
    } while (0)

    const float4* xp = reinterpret_cast<const float4*>(
        story + (size_t)b * (size_t)T * 3u);
    int nIter = (T * 3) / 12;  // 4 steps (12 floats = 3 float4) per iteration

    float4 ca = xp[0], cb = xp[1], cd = xp[2];
    // Prologue: xpart for step 0.
    {
        u64 X0 = pk2(ca.x, ca.x), X1 = pk2(ca.y, ca.y), X2 = pk2(ca.z, ca.z);
#pragma unroll
        for (int r = 0; r < 6; r++)
            XP[r] = fma2(WI0[r], X0, fma2(WI1[r], X1, fma2(WI2[r], X2, BS[r])));
    }

    for (int it = 1; it <= nIter; ++it) {
        float4 na, nb, nd;
        if (it < nIter) {              // prefetch next 4-step group
            na = xp[3 * it + 0];
            nb = xp[3 * it + 1];
            nd = xp[3 * it + 2];
        } else {
            na = ca; nb = cb; nd = cd; // dead values on last iteration
        }
        STEP(ca.w, cb.x, cb.y);        // step 4k   (XP -> step 4k+1)
        STEP(cb.z, cb.w, cd.x);        // step 4k+1 (XP -> step 4k+2)
        STEP(cd.y, cd.z, cd.w);        // step 4k+2 (XP -> step 4k+3)
        STEP(na.x, na.y, na.z);        // step 4k+3 (XP -> next group's step 0)
        ca = na; cb = nb; cd = nd;
    }
#undef STEP

    // Cosine similarities on H'=2h — scale-invariant, identical result.
    float nh = sqrtf(h0 * h0 + h1 * h1 + h2 * h2);
    nh = fmaxf(nh, 1e-8f);

    float a0 = __ldg(&e1g[3 * b + 0]);
    float a1 = __ldg(&e1g[3 * b + 1]);
    float a2 = __ldg(&e1g[3 * b + 2]);
    float n1 = fmaxf(sqrtf(a0 * a0 + a1 * a1 + a2 * a2), 1e-8f);
    float d1 = h0 * a0 + h1 * a1 + h2 * a2;

    float b0 = __ldg(&e2g[3 * b + 0]);
    float b1 = __ldg(&e2g[3 * b + 1]);
    float b2 = __ldg(&e2g[3 * b + 2]);
    float n2 = fmaxf(sqrtf(b0 * b0 + b1 * b1 + b2 * b2), 1e-8f);
    float d2 = h0 * b0 + h1 * b1 + h2 * b2;

    out[2 * b + 0] = d1 / (nh * n1);
    out[2 * b + 1] = d2 / (nh * n2);
}

extern "C" void kernel_launch(void* const* d_in, const int* in_sizes, int n_in,
                              void* d_out, int out_size)
{
    const float* story = (const float*)d_in[0];
    const float* e1    = (const float*)d_in[1];
    const float* e2    = (const float*)d_in[2];
    const float* Wih   = (const float*)d_in[3];
    const float* Whh   = (const float*)d_in[4];
    const float* bih   = (const float*)d_in[5];
    const float* bhh   = (const float*)d_in[6];

    int B = in_sizes[1] / 3;                 // ending1_emb is [B,3]
    int T = in_sizes[0] / (B * 3);           // story_emb is [B,T,3]

    int threads = 128;
    int blocks  = (B + threads - 1) / threads;
    lstm_cos_kernel<<<blocks, threads>>>(story, e1, e2, Wih, Whh, bih, bhh,
                                         (float*)d_out, B, T);
}